// round 13
// baseline (speedup 1.0000x reference)
#include <cuda_runtime.h>
#include <cuda_bf16.h>
#include <cstdint>

#define NB   8
#define CIN  256
#define COUT 4
#define ZD   32
#define VOX  (ZD*ZD*ZD)     // 32768
#define VOX4 (VOX/4)        // 8192
#define UD   64

#define CONV_BLOCKS 2048            // 256 per batch, batch-major
#define CONV_PER_BATCH 256
#define UP_PER_BATCH 512            // COUT * 128 tiles
#define UP_BLOCKS   (NB*UP_PER_BATCH)   // 4096

#define WE0 0.31756757f   // 1.175/3.7
#define WE1 0.61486486f   // 2.275/3.7
#define WE2 0.06756757f   // 0.25/3.7

__device__ float g_ybuf[NB * COUT * VOX];   // conv+residual result (4 MB)
__device__ int   g_done[NB];                // per-batch conv completion counters
__device__ int   g_up[NB];                  // per-batch upblur completion counters

#define CP_ASYNC16(sa, gp) \
    asm volatile("cp.async.cg.shared.global [%0], [%1], 16;" :: "r"(sa), "l"(gp) : "memory")
#define CP_COMMIT() asm volatile("cp.async.commit_group;" ::: "memory")
#define CP_WAIT7()  asm volatile("cp.async.wait_group 7;" ::: "memory")

__global__ void __launch_bounds__(128, 7) fused_kernel(
    const float* __restrict__ x, const float* __restrict__ S,
    const float* __restrict__ prev, const float* __restrict__ weight,
    float* __restrict__ out)
{
    const int bid = blockIdx.x;
    const int tid = threadIdx.x;

    if (bid < CONV_BLOCKS) {
        // ============== Phase 1: modulated 1x1x1 conv + residual ==============
        __shared__ float4 cw[CIN];            // 4 KB coeffs
        __shared__ float4 part[32][17];       // padded partials, 8.7 KB
        __shared__ float4 stage[4][8][32];    // [chunk][slot][lane], 16 KB

        const int b    = bid >> 8;            // batch-major!
        const int vblk = bid & 255;

        #pragma unroll
        for (int i = tid; i < CIN; i += 128) {
            const float s = S[b * CIN + i] + 1.0f;
            cw[i] = make_float4(weight[0 * CIN + i] * s,
                                weight[1 * CIN + i] * s,
                                weight[2 * CIN + i] * s,
                                weight[3 * CIN + i] * s);
        }
        __syncthreads();

        const int chunk = tid >> 5;           // warp id: channels [64*chunk, ..+64)
        const int vl    = tid & 31;
        const int v     = vblk * 32 + vl;
        const float4* xb = reinterpret_cast<const float4*>(x)
                         + (size_t)b * CIN * VOX4 + (size_t)(chunk * 64) * VOX4 + v;
        const float4* cc = cw + chunk * 64;

        // Thread-private smem slots (each thread loads & reads only its own lane).
        const unsigned int sbase =
            (unsigned int)__cvta_generic_to_shared(&stage[chunk][0][vl]);

        float4 a0 = make_float4(0.f, 0.f, 0.f, 0.f);
        float4 a1 = a0, a2 = a0, a3 = a0;

        // Prologue: 8 channels in flight (one commit group per channel).
        #pragma unroll
        for (int d = 0; d < 8; d++) {
            CP_ASYNC16(sbase + d * 512, xb + (size_t)d * VOX4);
            CP_COMMIT();
        }

        #pragma unroll 2
        for (int i0 = 0; i0 < 64; i0 += 8) {
            #pragma unroll
            for (int j = 0; j < 8; j++) {
                CP_WAIT7();                              // slot j (channel i0+j) ready
                const float4 xv = stage[chunk][j][vl];   // own lane only
                const float4 c  = cc[i0 + j];
                a0.x = fmaf(c.x, xv.x, a0.x); a0.y = fmaf(c.x, xv.y, a0.y);
                a0.z = fmaf(c.x, xv.z, a0.z); a0.w = fmaf(c.x, xv.w, a0.w);
                a1.x = fmaf(c.y, xv.x, a1.x); a1.y = fmaf(c.y, xv.y, a1.y);
                a1.z = fmaf(c.y, xv.z, a1.z); a1.w = fmaf(c.y, xv.w, a1.w);
                a2.x = fmaf(c.z, xv.x, a2.x); a2.y = fmaf(c.z, xv.y, a2.y);
                a2.z = fmaf(c.z, xv.z, a2.z); a2.w = fmaf(c.z, xv.w, a2.w);
                a3.x = fmaf(c.w, xv.x, a3.x); a3.y = fmaf(c.w, xv.y, a3.y);
                a3.z = fmaf(c.w, xv.z, a3.z); a3.w = fmaf(c.w, xv.w, a3.w);
                const int nx = i0 + j + 8;
                if (nx < 64)                             // refill slot j (read above)
                    CP_ASYNC16(sbase + j * 512, xb + (size_t)nx * VOX4);
                CP_COMMIT();                             // keep group count uniform
            }
        }

        part[vl][chunk * 4 + 0] = a0;
        part[vl][chunk * 4 + 1] = a1;
        part[vl][chunk * 4 + 2] = a2;
        part[vl][chunk * 4 + 3] = a3;
        __syncthreads();

        const int oc = chunk;
        float4 r0 = part[vl][0 * 4 + oc];
        float4 r1 = part[vl][1 * 4 + oc];
        float4 r2 = part[vl][2 * 4 + oc];
        float4 r3 = part[vl][3 * 4 + oc];
        float4 r;
        r.x = (r0.x + r1.x) + (r2.x + r3.x);
        r.y = (r0.y + r1.y) + (r2.y + r3.y);
        r.z = (r0.z + r1.z) + (r2.z + r3.z);
        r.w = (r0.w + r1.w) + (r2.w + r3.w);

        const size_t oidx = (size_t)b * COUT * VOX4 + (size_t)oc * VOX4 + v;
        float4 p = __ldcs(&reinterpret_cast<const float4*>(prev)[oidx]);
        r.x += p.x; r.y += p.y; r.z += p.z; r.w += p.w;
        reinterpret_cast<float4*>(g_ybuf)[oidx] = r;   // plain store: stays L2-hot

        __threadfence();          // release y stores
        __syncthreads();
        if (tid == 0) atomicAdd(&g_done[b], 1);

    } else {
        // ============== Phase 2: fused upsample x2 + blur ==============
        __shared__ float sm[4][6][35];     // [dz][dx][dy] halo, padded, 3.4 KB

        const int ub = bid - CONV_BLOCKS;
        const int bc = ub >> 7;            // 0..31 (b*COUT + c), batch-major
        const int t  = ub & 127;           // tile within bc
        const int zT = t >> 3;             // 0..15
        const int xT = t & 7;              // 0..7
        const int b  = bc >> 2;
        const int mz0 = zT * 2;
        const int mx0 = xT * 4;

        if (tid == 0) {
            while (*(volatile int*)&g_done[b] < CONV_PER_BATCH)
                __nanosleep(256);
        }
        __syncthreads();
        __threadfence();          // acquire y stores

        const float* __restrict__ yb = g_ybuf + (size_t)bc * VOX;

        for (int e = tid; e < 4 * 6 * 34; e += 128) {
            const int dz = e / (6 * 34);
            const int rr = e - dz * (6 * 34);
            const int dx = rr / 34;
            const int dy = rr - dx * 34;
            int gz = mz0 - 1 + dz; gz = gz < 0 ? 0 : (gz > ZD - 1 ? ZD - 1 : gz);
            int gx = mx0 - 1 + dx; gx = gx < 0 ? 0 : (gx > ZD - 1 ? ZD - 1 : gx);
            int gy = dy - 1;       gy = gy < 0 ? 0 : (gy > ZD - 1 ? ZD - 1 : gy);
            sm[dz][dx][dy] = yb[(gz * ZD + gx) * ZD + gy];
        }
        __syncthreads();

        const int ly2 = tid & 15;
        const int lx  = (tid >> 4) & 3;
        const int lz  = tid >> 6;
        const int y0  = 2 * ly2;

        float v[3][3][4];
        #pragma unroll
        for (int i = 0; i < 3; i++)
            #pragma unroll
            for (int j = 0; j < 3; j++)
                #pragma unroll
                for (int k = 0; k < 4; k++)
                    v[i][j][k] = sm[lz + i][lx + j][y0 + k];

        float sy[3][3][4];
        #pragma unroll
        for (int i = 0; i < 3; i++)
            #pragma unroll
            for (int j = 0; j < 3; j++) {
                sy[i][j][0] = fmaf(WE0, v[i][j][0], fmaf(WE1, v[i][j][1], WE2 * v[i][j][2]));
                sy[i][j][1] = fmaf(WE2, v[i][j][0], fmaf(WE1, v[i][j][1], WE0 * v[i][j][2]));
                sy[i][j][2] = fmaf(WE0, v[i][j][1], fmaf(WE1, v[i][j][2], WE2 * v[i][j][3]));
                sy[i][j][3] = fmaf(WE2, v[i][j][1], fmaf(WE1, v[i][j][2], WE0 * v[i][j][3]));
            }

        float sx[3][2][4];
        #pragma unroll
        for (int i = 0; i < 3; i++)
            #pragma unroll
            for (int k = 0; k < 4; k++) {
                sx[i][0][k] = fmaf(WE0, sy[i][0][k], fmaf(WE1, sy[i][1][k], WE2 * sy[i][2][k]));
                sx[i][1][k] = fmaf(WE2, sy[i][0][k], fmaf(WE1, sy[i][1][k], WE0 * sy[i][2][k]));
            }

        float r[2][2][4];
        #pragma unroll
        for (int px = 0; px < 2; px++)
            #pragma unroll
            for (int k = 0; k < 4; k++) {
                r[0][px][k] = fmaf(WE0, sx[0][px][k], fmaf(WE1, sx[1][px][k], WE2 * sx[2][px][k]));
                r[1][px][k] = fmaf(WE2, sx[0][px][k], fmaf(WE1, sx[1][px][k], WE0 * sx[2][px][k]));
            }

        const int mz = mz0 + lz;
        const int mx = mx0 + lx;
        float* ob = out + (size_t)bc * (UD * UD * UD);
        #pragma unroll
        for (int pz = 0; pz < 2; pz++)
            #pragma unroll
            for (int px = 0; px < 2; px++) {
                const size_t off = ((size_t)(2 * mz + pz) * UD + (2 * mx + px)) * UD + 4 * ly2;
                *reinterpret_cast<float4*>(ob + off) =
                    make_float4(r[pz][px][0], r[pz][px][1], r[pz][px][2], r[pz][px][3]);
            }

        // Self-reset for clean graph replays.
        __syncthreads();
        if (tid == 0) {
            const int done = atomicAdd(&g_up[b], 1);
            if (done == UP_PER_BATCH - 1) {
                g_done[b] = 0;
                g_up[b]   = 0;
                __threadfence();
            }
        }
    }
}

// ---------------------------------------------------------------------------
extern "C" void kernel_launch(void* const* d_in, const int* in_sizes, int n_in,
                              void* d_out, int out_size)
{
    const float* x      = (const float*)d_in[0];   // (8,256,32,32,32)
    const float* S      = (const float*)d_in[1];   // (8,256)
    const float* prev   = (const float*)d_in[2];   // (8,4,32,32,32)
    const float* weight = (const float*)d_in[3];   // (4,256)
    float* out = (float*)d_out;                    // (8,4,64,64,64)

    fused_kernel<<<CONV_BLOCKS + UP_BLOCKS, 128>>>(x, S, prev, weight, out);
}

// round 16
// speedup vs baseline: 1.1998x; 1.1998x over previous
#include <cuda_runtime.h>
#include <cuda_bf16.h>
#include <cstdint>

#define NB   8
#define CIN  256
#define COUT 4
#define ZD   32
#define VOX  (ZD*ZD*ZD)     // 32768
#define VOX4 (VOX/4)        // 8192
#define UD   64

#define CONV_BLOCKS 2048            // 256 per batch, batch-major
#define CONV_PER_BATCH 256
#define UP_PER_BATCH 256            // COUT * 64 tiles (4z x 4x x 32y cells each)
#define UP_BLOCKS   (NB*UP_PER_BATCH)   // 2048

// Collapsed upsample+blur 3-tap weights (constant everywhere incl. borders
// thanks to replicate-clamped halo): even output (WE0,WE1,WE2), odd mirrored.
#define WE0 0.31756757f   // 1.175/3.7
#define WE1 0.61486486f   // 2.275/3.7
#define WE2 0.06756757f   // 0.25/3.7

__device__ float g_ybuf[NB * COUT * VOX];   // conv+residual result (4 MB)
__device__ int   g_done[NB];                // per-batch conv completion counters
__device__ int   g_up[NB];                  // per-batch upblur completion counters

__global__ void __launch_bounds__(256, 5) fused_kernel(
    const float* __restrict__ x, const float* __restrict__ S,
    const float* __restrict__ prev, const float* __restrict__ weight,
    float* __restrict__ out)
{
    const int bid = blockIdx.x;
    const int tid = threadIdx.x;

    if (bid < CONV_BLOCKS) {
        // ============== Phase 1: modulated 1x1x1 conv + residual ==============
        // 128 active threads (R8 shape); threads 128..255 exit immediately so
        // the resident warp count per conv block stays 4 + 4 idle (idle warps
        // retire at the branch and free their slots).
        if (tid >= 128) return;

        __shared__ float4 cw[CIN];        // 4 KB coeffs
        __shared__ float4 part[32][17];   // padded partials, 8.7 KB

        const int b    = bid >> 8;        // batch-major!
        const int vblk = bid & 255;

        #pragma unroll
        for (int i = tid; i < CIN; i += 128) {
            const float s = S[b * CIN + i] + 1.0f;
            cw[i] = make_float4(weight[0 * CIN + i] * s,
                                weight[1 * CIN + i] * s,
                                weight[2 * CIN + i] * s,
                                weight[3 * CIN + i] * s);
        }
        __syncthreads();

        const int chunk = tid >> 5;              // 0..3 -> 64 channels each
        const int vl    = tid & 31;
        const int v     = vblk * 32 + vl;
        const float4* xb = reinterpret_cast<const float4*>(x)
                         + (size_t)b * CIN * VOX4 + (size_t)(chunk * 64) * VOX4 + v;
        const float4* cc = cw + chunk * 64;

        float4 a0 = make_float4(0.f, 0.f, 0.f, 0.f);
        float4 a1 = a0, a2 = a0, a3 = a0;

        // Double-buffered 4-deep load pipeline (R8, proven 4.88 TB/s).
        float4 xv0[4], xv1[4];
        #pragma unroll
        for (int j = 0; j < 4; j++)
            xv0[j] = __ldcs(&xb[(size_t)j * VOX4]);

        #pragma unroll
        for (int i0 = 0; i0 < 64; i0 += 8) {
            #pragma unroll
            for (int j = 0; j < 4; j++)
                xv1[j] = __ldcs(&xb[(size_t)(i0 + 4 + j) * VOX4]);
            #pragma unroll
            for (int j = 0; j < 4; j++) {
                const float4 c = cc[i0 + j];
                const float4 xv = xv0[j];
                a0.x = fmaf(c.x, xv.x, a0.x); a0.y = fmaf(c.x, xv.y, a0.y);
                a0.z = fmaf(c.x, xv.z, a0.z); a0.w = fmaf(c.x, xv.w, a0.w);
                a1.x = fmaf(c.y, xv.x, a1.x); a1.y = fmaf(c.y, xv.y, a1.y);
                a1.z = fmaf(c.y, xv.z, a1.z); a1.w = fmaf(c.y, xv.w, a1.w);
                a2.x = fmaf(c.z, xv.x, a2.x); a2.y = fmaf(c.z, xv.y, a2.y);
                a2.z = fmaf(c.z, xv.z, a2.z); a2.w = fmaf(c.z, xv.w, a2.w);
                a3.x = fmaf(c.w, xv.x, a3.x); a3.y = fmaf(c.w, xv.y, a3.y);
                a3.z = fmaf(c.w, xv.z, a3.z); a3.w = fmaf(c.w, xv.w, a3.w);
            }
            if (i0 < 56) {
                #pragma unroll
                for (int j = 0; j < 4; j++)
                    xv0[j] = __ldcs(&xb[(size_t)(i0 + 8 + j) * VOX4]);
            }
            #pragma unroll
            for (int j = 0; j < 4; j++) {
                const float4 c = cc[i0 + 4 + j];
                const float4 xv = xv1[j];
                a0.x = fmaf(c.x, xv.x, a0.x); a0.y = fmaf(c.x, xv.y, a0.y);
                a0.z = fmaf(c.x, xv.z, a0.z); a0.w = fmaf(c.x, xv.w, a0.w);
                a1.x = fmaf(c.y, xv.x, a1.x); a1.y = fmaf(c.y, xv.y, a1.y);
                a1.z = fmaf(c.y, xv.z, a1.z); a1.w = fmaf(c.y, xv.w, a1.w);
                a2.x = fmaf(c.z, xv.x, a2.x); a2.y = fmaf(c.z, xv.y, a2.y);
                a2.z = fmaf(c.z, xv.z, a2.z); a2.w = fmaf(c.z, xv.w, a2.w);
                a3.x = fmaf(c.w, xv.x, a3.x); a3.y = fmaf(c.w, xv.y, a3.y);
                a3.z = fmaf(c.w, xv.z, a3.z); a3.w = fmaf(c.w, xv.w, a3.w);
            }
        }

        part[vl][chunk * 4 + 0] = a0;
        part[vl][chunk * 4 + 1] = a1;
        part[vl][chunk * 4 + 2] = a2;
        part[vl][chunk * 4 + 3] = a3;
        __syncthreads();

        const int oc = chunk;
        float4 r0 = part[vl][0 * 4 + oc];
        float4 r1 = part[vl][1 * 4 + oc];
        float4 r2 = part[vl][2 * 4 + oc];
        float4 r3 = part[vl][3 * 4 + oc];
        float4 r;
        r.x = (r0.x + r1.x) + (r2.x + r3.x);
        r.y = (r0.y + r1.y) + (r2.y + r3.y);
        r.z = (r0.z + r1.z) + (r2.z + r3.z);
        r.w = (r0.w + r1.w) + (r2.w + r3.w);

        const size_t oidx = (size_t)b * COUT * VOX4 + (size_t)oc * VOX4 + v;
        float4 p = __ldcs(&reinterpret_cast<const float4*>(prev)[oidx]);
        r.x += p.x; r.y += p.y; r.z += p.z; r.w += p.w;
        reinterpret_cast<float4*>(g_ybuf)[oidx] = r;   // plain store: stays L2-hot

        __threadfence();          // release y stores
        __syncthreads();
        if (tid == 0) atomicAdd(&g_done[b], 1);

    } else {
        // ============== Phase 2: fused upsample x2 + blur (256 thr) ==============
        __shared__ float sm[6][6][35];     // [dz][dx][dy] halo, padded, 5 KB

        const int ub = bid - CONV_BLOCKS;
        const int bc = ub >> 6;            // 0..31 (b*COUT + c), batch-major
        const int t  = ub & 63;            // tile within bc
        const int zT = t >> 3;             // 0..7
        const int xT = t & 7;              // 0..7
        const int b  = bc >> 2;
        const int mz0 = zT * 4;
        const int mx0 = xT * 4;

        // Wait for this batch's conv (producers have lower bids -> no deadlock).
        if (tid == 0) {
            while (*(volatile int*)&g_done[b] < CONV_PER_BATCH)
                __nanosleep(256);
        }
        __syncthreads();
        __threadfence();          // acquire y stores

        const float* __restrict__ yb = g_ybuf + (size_t)bc * VOX;

        // Replicate-clamped halo: z,x in [t0-1, t0+4], y in [-1, 32].
        // 6*6*34 = 1224 elements.
        for (int e = tid; e < 6 * 6 * 34; e += 256) {
            const int dz = e / (6 * 34);
            const int rr = e - dz * (6 * 34);
            const int dx = rr / 34;
            const int dy = rr - dx * 34;
            int gz = mz0 - 1 + dz; gz = gz < 0 ? 0 : (gz > ZD - 1 ? ZD - 1 : gz);
            int gx = mx0 - 1 + dx; gx = gx < 0 ? 0 : (gx > ZD - 1 ? ZD - 1 : gx);
            int gy = dy - 1;       gy = gy < 0 ? 0 : (gy > ZD - 1 ? ZD - 1 : gy);
            sm[dz][dx][dy] = yb[(gz * ZD + gx) * ZD + gy];
        }
        __syncthreads();

        const int ly2 = tid & 15;          // y cell-pair index
        const int lx  = (tid >> 4) & 3;
        const int lz  = tid >> 6;          // 0..3
        const int y0  = 2 * ly2;

        float v[3][3][4];
        #pragma unroll
        for (int i = 0; i < 3; i++)
            #pragma unroll
            for (int j = 0; j < 3; j++)
                #pragma unroll
                for (int k = 0; k < 4; k++)
                    v[i][j][k] = sm[lz + i][lx + j][y0 + k];

        float sy[3][3][4];
        #pragma unroll
        for (int i = 0; i < 3; i++)
            #pragma unroll
            for (int j = 0; j < 3; j++) {
                sy[i][j][0] = fmaf(WE0, v[i][j][0], fmaf(WE1, v[i][j][1], WE2 * v[i][j][2]));
                sy[i][j][1] = fmaf(WE2, v[i][j][0], fmaf(WE1, v[i][j][1], WE0 * v[i][j][2]));
                sy[i][j][2] = fmaf(WE0, v[i][j][1], fmaf(WE1, v[i][j][2], WE2 * v[i][j][3]));
                sy[i][j][3] = fmaf(WE2, v[i][j][1], fmaf(WE1, v[i][j][2], WE0 * v[i][j][3]));
            }

        float sx[3][2][4];
        #pragma unroll
        for (int i = 0; i < 3; i++)
            #pragma unroll
            for (int k = 0; k < 4; k++) {
                sx[i][0][k] = fmaf(WE0, sy[i][0][k], fmaf(WE1, sy[i][1][k], WE2 * sy[i][2][k]));
                sx[i][1][k] = fmaf(WE2, sy[i][0][k], fmaf(WE1, sy[i][1][k], WE0 * sy[i][2][k]));
            }

        float r[2][2][4];
        #pragma unroll
        for (int px = 0; px < 2; px++)
            #pragma unroll
            for (int k = 0; k < 4; k++) {
                r[0][px][k] = fmaf(WE0, sx[0][px][k], fmaf(WE1, sx[1][px][k], WE2 * sx[2][px][k]));
                r[1][px][k] = fmaf(WE2, sx[0][px][k], fmaf(WE1, sx[1][px][k], WE0 * sx[2][px][k]));
            }

        const int mz = mz0 + lz;
        const int mx = mx0 + lx;
        float* ob = out + (size_t)bc * (UD * UD * UD);
        #pragma unroll
        for (int pz = 0; pz < 2; pz++)
            #pragma unroll
            for (int px = 0; px < 2; px++) {
                const size_t off = ((size_t)(2 * mz + pz) * UD + (2 * mx + px)) * UD + 4 * ly2;
                *reinterpret_cast<float4*>(ob + off) =
                    make_float4(r[pz][px][0], r[pz][px][1], r[pz][px][2], r[pz][px][3]);
            }

        // Self-reset: last upblur block of batch b zeroes the counters
        // (safe: g_up[b] reaches UP_PER_BATCH-1 only after every consumer
        // of b passed its spin). Next graph replay starts clean.
        __syncthreads();
        if (tid == 0) {
            const int done = atomicAdd(&g_up[b], 1);
            if (done == UP_PER_BATCH - 1) {
                g_done[b] = 0;
                g_up[b]   = 0;
                __threadfence();
            }
        }
    }
}

// ---------------------------------------------------------------------------
extern "C" void kernel_launch(void* const* d_in, const int* in_sizes, int n_in,
                              void* d_out, int out_size)
{
    const float* x      = (const float*)d_in[0];   // (8,256,32,32,32)
    const float* S      = (const float*)d_in[1];   // (8,256)
    const float* prev   = (const float*)d_in[2];   // (8,4,32,32,32)
    const float* weight = (const float*)d_in[3];   // (4,256)
    float* out = (float*)d_out;                    // (8,4,64,64,64)

    fused_kernel<<<CONV_BLOCKS + UP_BLOCKS, 256>>>(x, S, prev, weight, out);
}

// round 17
// speedup vs baseline: 1.2088x; 1.0075x over previous
#include <cuda_runtime.h>
#include <cuda_bf16.h>
#include <cstdint>

#define NB   8
#define CIN  256
#define COUT 4
#define ZD   32
#define VOX  (ZD*ZD*ZD)     // 32768
#define VOX4 (VOX/4)        // 8192
#define UD   64

#define CONV_BLOCKS 2048            // 256 per batch, batch-major
#define CONV_PER_BATCH 256
#define UP_PER_BATCH 256            // COUT * 64 tiles (4z x 4x x 32y cells each)
#define UP_BLOCKS   (NB*UP_PER_BATCH)   // 2048

// Collapsed upsample+blur 3-tap weights (constant everywhere incl. borders
// thanks to replicate-clamped halo): even output (WE0,WE1,WE2), odd mirrored.
#define WE0 0.31756757f   // 1.175/3.7
#define WE1 0.61486486f   // 2.275/3.7
#define WE2 0.06756757f   // 0.25/3.7

__device__ float g_ybuf[NB * COUT * VOX];   // conv+residual result (4 MB)
__device__ int   g_done[NB];                // per-batch conv completion counters
__device__ int   g_up[NB];                  // per-batch upblur completion counters

__global__ void __launch_bounds__(256, 5) fused_kernel(
    const float* __restrict__ x, const float* __restrict__ S,
    const float* __restrict__ prev, const float* __restrict__ weight,
    float* __restrict__ out)
{
    const int bid = blockIdx.x;
    const int tid = threadIdx.x;

    if (bid < CONV_BLOCKS) {
        // ============== Phase 1: modulated 1x1x1 conv + residual ==============
        // 8 warps, 32 channels per warp, 4-deep double-buffered pipeline.
        __shared__ float4 cw[CIN];        // 4 KB coeffs
        __shared__ float4 part[32][33];   // [vl][chunk*4+oc], padded: 16.9 KB

        const int b    = bid >> 8;        // batch-major!
        const int vblk = bid & 255;

        {
            const int i = tid;            // 256 threads, one coeff each
            const float s = S[b * CIN + i] + 1.0f;
            cw[i] = make_float4(weight[0 * CIN + i] * s,
                                weight[1 * CIN + i] * s,
                                weight[2 * CIN + i] * s,
                                weight[3 * CIN + i] * s);
        }
        __syncthreads();

        const int chunk = tid >> 5;              // 0..7 -> 32 channels each
        const int vl    = tid & 31;
        const int v     = vblk * 32 + vl;
        const float4* xb = reinterpret_cast<const float4*>(x)
                         + (size_t)b * CIN * VOX4 + (size_t)(chunk * 32) * VOX4 + v;
        const float4* cc = cw + chunk * 32;

        float4 a0 = make_float4(0.f, 0.f, 0.f, 0.f);
        float4 a1 = a0, a2 = a0, a3 = a0;

        // Double-buffered 4-deep load pipeline (proven depth).
        float4 xv0[4], xv1[4];
        #pragma unroll
        for (int j = 0; j < 4; j++)
            xv0[j] = __ldcs(&xb[(size_t)j * VOX4]);

        #pragma unroll
        for (int i0 = 0; i0 < 32; i0 += 8) {
            #pragma unroll
            for (int j = 0; j < 4; j++)
                xv1[j] = __ldcs(&xb[(size_t)(i0 + 4 + j) * VOX4]);
            #pragma unroll
            for (int j = 0; j < 4; j++) {
                const float4 c = cc[i0 + j];
                const float4 xv = xv0[j];
                a0.x = fmaf(c.x, xv.x, a0.x); a0.y = fmaf(c.x, xv.y, a0.y);
                a0.z = fmaf(c.x, xv.z, a0.z); a0.w = fmaf(c.x, xv.w, a0.w);
                a1.x = fmaf(c.y, xv.x, a1.x); a1.y = fmaf(c.y, xv.y, a1.y);
                a1.z = fmaf(c.y, xv.z, a1.z); a1.w = fmaf(c.y, xv.w, a1.w);
                a2.x = fmaf(c.z, xv.x, a2.x); a2.y = fmaf(c.z, xv.y, a2.y);
                a2.z = fmaf(c.z, xv.z, a2.z); a2.w = fmaf(c.z, xv.w, a2.w);
                a3.x = fmaf(c.w, xv.x, a3.x); a3.y = fmaf(c.w, xv.y, a3.y);
                a3.z = fmaf(c.w, xv.z, a3.z); a3.w = fmaf(c.w, xv.w, a3.w);
            }
            if (i0 < 24) {
                #pragma unroll
                for (int j = 0; j < 4; j++)
                    xv0[j] = __ldcs(&xb[(size_t)(i0 + 8 + j) * VOX4]);
            }
            #pragma unroll
            for (int j = 0; j < 4; j++) {
                const float4 c = cc[i0 + 4 + j];
                const float4 xv = xv1[j];
                a0.x = fmaf(c.x, xv.x, a0.x); a0.y = fmaf(c.x, xv.y, a0.y);
                a0.z = fmaf(c.x, xv.z, a0.z); a0.w = fmaf(c.x, xv.w, a0.w);
                a1.x = fmaf(c.y, xv.x, a1.x); a1.y = fmaf(c.y, xv.y, a1.y);
                a1.z = fmaf(c.y, xv.z, a1.z); a1.w = fmaf(c.y, xv.w, a1.w);
                a2.x = fmaf(c.z, xv.x, a2.x); a2.y = fmaf(c.z, xv.y, a2.y);
                a2.z = fmaf(c.z, xv.z, a2.z); a2.w = fmaf(c.z, xv.w, a2.w);
                a3.x = fmaf(c.w, xv.x, a3.x); a3.y = fmaf(c.w, xv.y, a3.y);
                a3.z = fmaf(c.w, xv.z, a3.z); a3.w = fmaf(c.w, xv.w, a3.w);
            }
        }

        part[vl][chunk * 4 + 0] = a0;
        part[vl][chunk * 4 + 1] = a1;
        part[vl][chunk * 4 + 2] = a2;
        part[vl][chunk * 4 + 3] = a3;
        __syncthreads();

        // First 128 threads: thread (oc, vl) sums 8 chunk partials.
        if (tid < 128) {
            const int rvl = tid & 31;
            const int oc  = tid >> 5;          // 0..3
            float4 r = part[rvl][0 * 4 + oc];
            #pragma unroll
            for (int ch = 1; ch < 8; ch++) {
                const float4 p = part[rvl][ch * 4 + oc];
                r.x += p.x; r.y += p.y; r.z += p.z; r.w += p.w;
            }

            const size_t oidx = (size_t)b * COUT * VOX4 + (size_t)oc * VOX4
                              + (size_t)(vblk * 32 + rvl);
            const float4 p = __ldcs(&reinterpret_cast<const float4*>(prev)[oidx]);
            r.x += p.x; r.y += p.y; r.z += p.z; r.w += p.w;
            reinterpret_cast<float4*>(g_ybuf)[oidx] = r;   // stays L2-hot
        }

        __threadfence();          // release y stores
        __syncthreads();
        if (tid == 0) atomicAdd(&g_done[b], 1);

    } else {
        // ============== Phase 2: fused upsample x2 + blur (256 thr) ==============
        __shared__ float sm[6][6][35];     // [dz][dx][dy] halo, padded, 5 KB

        const int ub = bid - CONV_BLOCKS;
        const int bc = ub >> 6;            // 0..31 (b*COUT + c), batch-major
        const int t  = ub & 63;            // tile within bc
        const int zT = t >> 3;             // 0..7
        const int xT = t & 7;              // 0..7
        const int b  = bc >> 2;
        const int mz0 = zT * 4;
        const int mx0 = xT * 4;

        // Wait for this batch's conv (producers have lower bids -> no deadlock).
        if (tid == 0) {
            while (*(volatile int*)&g_done[b] < CONV_PER_BATCH)
                __nanosleep(256);
        }
        __syncthreads();
        __threadfence();          // acquire y stores

        const float* __restrict__ yb = g_ybuf + (size_t)bc * VOX;

        // Replicate-clamped halo: z,x in [t0-1, t0+4], y in [-1, 32].
        for (int e = tid; e < 6 * 6 * 34; e += 256) {
            const int dz = e / (6 * 34);
            const int rr = e - dz * (6 * 34);
            const int dx = rr / 34;
            const int dy = rr - dx * 34;
            int gz = mz0 - 1 + dz; gz = gz < 0 ? 0 : (gz > ZD - 1 ? ZD - 1 : gz);
            int gx = mx0 - 1 + dx; gx = gx < 0 ? 0 : (gx > ZD - 1 ? ZD - 1 : gx);
            int gy = dy - 1;       gy = gy < 0 ? 0 : (gy > ZD - 1 ? ZD - 1 : gy);
            sm[dz][dx][dy] = yb[(gz * ZD + gx) * ZD + gy];
        }
        __syncthreads();

        const int ly2 = tid & 15;          // y cell-pair index
        const int lx  = (tid >> 4) & 3;
        const int lz  = tid >> 6;          // 0..3
        const int y0  = 2 * ly2;

        float v[3][3][4];
        #pragma unroll
        for (int i = 0; i < 3; i++)
            #pragma unroll
            for (int j = 0; j < 3; j++)
                #pragma unroll
                for (int k = 0; k < 4; k++)
                    v[i][j][k] = sm[lz + i][lx + j][y0 + k];

        float sy[3][3][4];
        #pragma unroll
        for (int i = 0; i < 3; i++)
            #pragma unroll
            for (int j = 0; j < 3; j++) {
                sy[i][j][0] = fmaf(WE0, v[i][j][0], fmaf(WE1, v[i][j][1], WE2 * v[i][j][2]));
                sy[i][j][1] = fmaf(WE2, v[i][j][0], fmaf(WE1, v[i][j][1], WE0 * v[i][j][2]));
                sy[i][j][2] = fmaf(WE0, v[i][j][1], fmaf(WE1, v[i][j][2], WE2 * v[i][j][3]));
                sy[i][j][3] = fmaf(WE2, v[i][j][1], fmaf(WE1, v[i][j][2], WE0 * v[i][j][3]));
            }

        float sx[3][2][4];
        #pragma unroll
        for (int i = 0; i < 3; i++)
            #pragma unroll
            for (int k = 0; k < 4; k++) {
                sx[i][0][k] = fmaf(WE0, sy[i][0][k], fmaf(WE1, sy[i][1][k], WE2 * sy[i][2][k]));
                sx[i][1][k] = fmaf(WE2, sy[i][0][k], fmaf(WE1, sy[i][1][k], WE0 * sy[i][2][k]));
            }

        float r[2][2][4];
        #pragma unroll
        for (int px = 0; px < 2; px++)
            #pragma unroll
            for (int k = 0; k < 4; k++) {
                r[0][px][k] = fmaf(WE0, sx[0][px][k], fmaf(WE1, sx[1][px][k], WE2 * sx[2][px][k]));
                r[1][px][k] = fmaf(WE2, sx[0][px][k], fmaf(WE1, sx[1][px][k], WE0 * sx[2][px][k]));
            }

        const int mz = mz0 + lz;
        const int mx = mx0 + lx;
        float* ob = out + (size_t)bc * (UD * UD * UD);
        #pragma unroll
        for (int pz = 0; pz < 2; pz++)
            #pragma unroll
            for (int px = 0; px < 2; px++) {
                const size_t off = ((size_t)(2 * mz + pz) * UD + (2 * mx + px)) * UD + 4 * ly2;
                *reinterpret_cast<float4*>(ob + off) =
                    make_float4(r[pz][px][0], r[pz][px][1], r[pz][px][2], r[pz][px][3]);
            }

        // Self-reset: last upblur block of batch b zeroes the counters
        // (safe: g_up[b] reaches UP_PER_BATCH-1 only after every consumer
        // of b passed its spin). Next graph replay starts clean.
        __syncthreads();
        if (tid == 0) {
            const int done = atomicAdd(&g_up[b], 1);
            if (done == UP_PER_BATCH - 1) {
                g_done[b] = 0;
                g_up[b]   = 0;
                __threadfence();
            }
        }
    }
}

// ---------------------------------------------------------------------------
extern "C" void kernel_launch(void* const* d_in, const int* in_sizes, int n_in,
                              void* d_out, int out_size)
{
    const float* x      = (const float*)d_in[0];   // (8,256,32,32,32)
    const float* S      = (const float*)d_in[1];   // (8,256)
    const float* prev   = (const float*)d_in[2];   // (8,4,32,32,32)
    const float* weight = (const float*)d_in[3];   // (4,256)
    float* out = (float*)d_out;                    // (8,4,64,64,64)

    fused_kernel<<<CONV_BLOCKS + UP_BLOCKS, 256>>>(x, S, prev, weight, out);
}